// round 1
// baseline (speedup 1.0000x reference)
#include <cuda_runtime.h>
#include <math.h>

// Problem constants
#define BB   8
#define TT   2048
#define EE   256
#define HH   4
#define HD   64
#define PP   8
#define BT   (BB*TT)          // 16384

// ---------------- scratch (device globals; no allocation allowed) -----------
__device__ float g_h[BT*EE];
__device__ float g_q[BT*EE];   // [B][H][T][HD]
__device__ float g_k[BT*EE];
__device__ float g_v[BT*EE];
__device__ float g_ao[BT*EE];  // [B][T][E]
__device__ float g_bs[BT];
__device__ float g_weff[EE+1]; // w_eff[256] + b_eff

// ---------------------------------------------------------------------------
// w_eff[j] = sum_i w_bd[i] * w_o[i][j];  b_eff = sum_i w_bd[i]*b_o[i] + b_bd
__global__ void weff_kernel(const float* __restrict__ w_o,
                            const float* __restrict__ w_bd,
                            const float* __restrict__ b_o,
                            const float* __restrict__ b_bd)
{
    int j = threadIdx.x;
    float s = 0.f;
    for (int i = 0; i < EE; i++) s += w_bd[i] * w_o[i*EE + j];
    g_weff[j] = s;
    if (j == 0) {
        float bb = b_bd[0];
        for (int i = 0; i < EE; i++) bb += w_bd[i] * b_o[i];
        g_weff[EE] = bb;
    }
}

// ---------------------------------------------------------------------------
// out[m][n] = sum_k A[m][k]*W[n][k] + bias[n]
// A: [M][256], W: [256][256]. 64x64 tile per block, 256 threads, 4x4/thread.
// qkv_mode: 0 -> out row-major [M][256]; 1 -> out [B][H][T][HD]
__global__ __launch_bounds__(256) void gemm256(const float* __restrict__ A,
                                               const float* __restrict__ W,
                                               const float* __restrict__ bias,
                                               float* __restrict__ out,
                                               int qkv_mode)
{
    __shared__ float As[16][64];   // [k][row]
    __shared__ float Ws[16][64];   // [k][col]
    const int m0 = blockIdx.x * 64;
    const int n0 = blockIdx.y * 64;
    const int tid = threadIdx.x;
    const int ty = tid >> 4, tx = tid & 15;
    const int lr = tid >> 2;              // 0..63
    const int lc = (tid & 3) << 2;        // 0,4,8,12

    float acc[4][4];
#pragma unroll
    for (int i = 0; i < 4; i++)
#pragma unroll
        for (int j = 0; j < 4; j++) acc[i][j] = 0.f;

    const float* Ap = A + (size_t)(m0 + lr) * EE + lc;
    const float* Wp = W + (size_t)(n0 + lr) * EE + lc;

    for (int k0 = 0; k0 < EE; k0 += 16) {
        float4 av = *(const float4*)(Ap + k0);
        float4 wv = *(const float4*)(Wp + k0);
        __syncthreads();
        As[lc+0][lr] = av.x; As[lc+1][lr] = av.y; As[lc+2][lr] = av.z; As[lc+3][lr] = av.w;
        Ws[lc+0][lr] = wv.x; Ws[lc+1][lr] = wv.y; Ws[lc+2][lr] = wv.z; Ws[lc+3][lr] = wv.w;
        __syncthreads();
#pragma unroll
        for (int kk = 0; kk < 16; kk++) {
            float4 a4 = *(const float4*)&As[kk][ty << 2];
            float4 w4 = *(const float4*)&Ws[kk][tx << 2];
            float ar[4] = {a4.x, a4.y, a4.z, a4.w};
            float wr[4] = {w4.x, w4.y, w4.z, w4.w};
#pragma unroll
            for (int i = 0; i < 4; i++)
#pragma unroll
                for (int j = 0; j < 4; j++) acc[i][j] += ar[i] * wr[j];
        }
    }

    float bn[4];
#pragma unroll
    for (int j = 0; j < 4; j++) bn[j] = bias[n0 + (tx << 2) + j];

    if (!qkv_mode) {
#pragma unroll
        for (int i = 0; i < 4; i++) {
            int row = m0 + (ty << 2) + i;
#pragma unroll
            for (int j = 0; j < 4; j++)
                out[(size_t)row * EE + n0 + (tx << 2) + j] = acc[i][j] + bn[j];
        }
    } else {
#pragma unroll
        for (int i = 0; i < 4; i++) {
            int row = m0 + (ty << 2) + i;
            int b = row >> 11, t = row & (TT - 1);
#pragma unroll
            for (int j = 0; j < 4; j++) {
                int n = n0 + (tx << 2) + j;
                int hh = n >> 6, d = n & 63;
                out[(size_t)(((b << 2) + hh) * TT + t) * HD + d] = acc[i][j] + bn[j];
            }
        }
    }
}

// ---------------------------------------------------------------------------
// Flash attention, fp32. Block = 64 query rows for one (b,h). 256 threads.
// Qs/Ks stored [d][row] for fragment loads; Ps aliases Ks; Vs is [kv][d].
__global__ __launch_bounds__(256) void attn_kernel(const float* __restrict__ q,
                                                   const float* __restrict__ k,
                                                   const float* __restrict__ v,
                                                   float* __restrict__ ao)
{
    __shared__ float Qs[64][64];
    __shared__ float KPs[64][64];
    __shared__ float Vs[64][64];

    const int qt0 = blockIdx.x * 64;
    const int bh  = blockIdx.y;                  // b*H + h
    const float* Q = q + (size_t)bh * TT * HD;
    const float* K = k + (size_t)bh * TT * HD;
    const float* V = v + (size_t)bh * TT * HD;

    const int tid = threadIdx.x;
    const int ty = tid >> 4, tx = tid & 15;
    const int lr = tid >> 2;
    const int lc0 = (tid & 3) << 2;

    // load Q tile, transposed + scaled
#pragma unroll
    for (int cc = 0; cc < 4; cc++) {
        int c = lc0 + cc * 16;
        float4 t4 = *(const float4*)(Q + (size_t)(qt0 + lr) * HD + c);
        Qs[c+0][lr] = t4.x * 0.125f; Qs[c+1][lr] = t4.y * 0.125f;
        Qs[c+2][lr] = t4.z * 0.125f; Qs[c+3][lr] = t4.w * 0.125f;
    }

    float m_i[4], l_i[4], o[4][4];
#pragma unroll
    for (int i = 0; i < 4; i++) {
        m_i[i] = -1e30f; l_i[i] = 0.f;
#pragma unroll
        for (int j = 0; j < 4; j++) o[i][j] = 0.f;
    }

    for (int kt = 0; kt < TT; kt += 64) {
        __syncthreads();   // protect KPs/Vs from previous iteration's readers
#pragma unroll
        for (int cc = 0; cc < 4; cc++) {
            int c = lc0 + cc * 16;
            float4 t4 = *(const float4*)(K + (size_t)(kt + lr) * HD + c);
            KPs[c+0][lr] = t4.x; KPs[c+1][lr] = t4.y;
            KPs[c+2][lr] = t4.z; KPs[c+3][lr] = t4.w;
            *(float4*)&Vs[lr][c] = *(const float4*)(V + (size_t)(kt + lr) * HD + c);
        }
        __syncthreads();

        // S = Q K^T  (64x64)
        float s[4][4];
#pragma unroll
        for (int i = 0; i < 4; i++)
#pragma unroll
            for (int j = 0; j < 4; j++) s[i][j] = 0.f;
#pragma unroll 8
        for (int kk = 0; kk < 64; kk++) {
            float4 a4 = *(const float4*)&Qs[kk][ty << 2];
            float4 b4 = *(const float4*)&KPs[kk][tx << 2];
            float ar[4] = {a4.x, a4.y, a4.z, a4.w};
            float br[4] = {b4.x, b4.y, b4.z, b4.w};
#pragma unroll
            for (int i = 0; i < 4; i++)
#pragma unroll
                for (int j = 0; j < 4; j++) s[i][j] += ar[i] * br[j];
        }

        // online softmax (row groups = 16 lanes sharing ty)
#pragma unroll
        for (int i = 0; i < 4; i++) {
            float rmax = fmaxf(fmaxf(s[i][0], s[i][1]), fmaxf(s[i][2], s[i][3]));
#pragma unroll
            for (int msk = 8; msk >= 1; msk >>= 1)
                rmax = fmaxf(rmax, __shfl_xor_sync(0xffffffffu, rmax, msk));
            float mn = fmaxf(m_i[i], rmax);
            float alpha = __expf(m_i[i] - mn);
            float psum = 0.f;
#pragma unroll
            for (int j = 0; j < 4; j++) { s[i][j] = __expf(s[i][j] - mn); psum += s[i][j]; }
#pragma unroll
            for (int msk = 8; msk >= 1; msk >>= 1)
                psum += __shfl_xor_sync(0xffffffffu, psum, msk);
            l_i[i] = l_i[i] * alpha + psum;
            m_i[i] = mn;
#pragma unroll
            for (int j = 0; j < 4; j++) o[i][j] *= alpha;
        }

        __syncthreads();   // everyone done reading KPs as K
#pragma unroll
        for (int i = 0; i < 4; i++)
#pragma unroll
            for (int j = 0; j < 4; j++)
                KPs[(tx << 2) + j][(ty << 2) + i] = s[i][j];   // Ps[kv][row]
        __syncthreads();

        // O += P V  (64x64)
#pragma unroll 8
        for (int kv = 0; kv < 64; kv++) {
            float4 p4 = *(const float4*)&KPs[kv][ty << 2];
            float4 v4 = *(const float4*)&Vs[kv][tx << 2];
            float pr[4] = {p4.x, p4.y, p4.z, p4.w};
            float vr[4] = {v4.x, v4.y, v4.z, v4.w};
#pragma unroll
            for (int i = 0; i < 4; i++)
#pragma unroll
                for (int j = 0; j < 4; j++) o[i][j] += pr[i] * vr[j];
        }
    }

    const int b = bh >> 2, hh = bh & 3;
#pragma unroll
    for (int i = 0; i < 4; i++) {
        float inv = 1.0f / l_i[i];
        int row = qt0 + (ty << 2) + i;
        float* dst = g_ao + (size_t)(b * TT + row) * EE + hh * HD + (tx << 2);
#pragma unroll
        for (int j = 0; j < 4; j++) dst[j] = o[i][j] * inv;
    }
    (void)ao;
}

// ---------------------------------------------------------------------------
// bs[t] = sigmoid(ao[t]·w_eff + b_eff). One warp per token.
__global__ __launch_bounds__(256) void bs_kernel()
{
    int t = blockIdx.x * 8 + (threadIdx.x >> 5);
    int lane = threadIdx.x & 31;
    const float* row = g_ao + (size_t)t * EE;
    float z = 0.f;
#pragma unroll
    for (int j = lane; j < EE; j += 32) z += row[j] * g_weff[j];
#pragma unroll
    for (int msk = 16; msk >= 1; msk >>= 1)
        z += __shfl_xor_sync(0xffffffffu, z, msk);
    if (lane == 0) {
        z += g_weff[EE];
        g_bs[t] = 1.0f / (1.0f + expf(-z));
    }
}

// ---------------------------------------------------------------------------
// Per batch: fp64 cumsum -> pid -> contiguous-range segment means -> w_pr proj
__global__ __launch_bounds__(256) void finalize_kernel(const float* __restrict__ w_pr,
                                                       const float* __restrict__ b_pr,
                                                       float* __restrict__ out)
{
    __shared__ float  sc[TT];
    __shared__ double sd[TT];
    __shared__ unsigned char pids[TT];
    __shared__ int starts[PP + 1];
    __shared__ float pe[PP][EE];

    const int b = blockIdx.x;
    const int tid = threadIdx.x;

    for (int t = tid; t < TT; t += 256) sc[t] = g_bs[b * TT + t];
    __syncthreads();

    if (tid == 0) {
        double c = 0.0;
        for (int t = 0; t < TT; t++) { c += (double)sc[t]; sd[t] = c; }
    }
    __syncthreads();

    double total = sd[TT - 1];
    double inv = 1.0 / fmax(total, 1e-6);
    for (int t = tid; t < TT; t += 256) {
        int p = (int)(sd[t] * inv * (double)PP);
        pids[t] = (unsigned char)(p > PP - 1 ? PP - 1 : p);
    }
    __syncthreads();

    if (tid == 0) {
        int cur = pids[0];
        for (int p = 0; p <= cur; p++) starts[p] = 0;
        for (int t = 1; t < TT; t++) {
            int p = pids[t];
            while (cur < p) starts[++cur] = t;
        }
        while (cur < PP) starts[++cur] = TT;
    }
    __syncthreads();

    // segment means; thread owns dim d = tid
    const float* hb = g_h + (size_t)b * TT * EE;
    for (int p = 0; p < PP; p++) {
        int s0 = starts[p], s1 = starts[p + 1];
        float a0 = 0.f, a1 = 0.f;
        int t = s0;
        for (; t + 1 < s1; t += 2) {
            a0 += hb[(size_t)t * EE + tid];
            a1 += hb[(size_t)(t + 1) * EE + tid];
        }
        if (t < s1) a0 += hb[(size_t)t * EE + tid];
        float cnt = (float)(s1 - s0);
        pe[p][tid] = (a0 + a1) / fmaxf(cnt, 1.0f);
    }
    __syncthreads();

    // out[b][p][n] = pe[p]·w_pr[n] + b_pr[n]; thread owns n = tid
    float bn = b_pr[tid];
    const float* wrow = w_pr + (size_t)tid * EE;
    for (int p = 0; p < PP; p++) {
        float a0 = 0.f, a1 = 0.f;
#pragma unroll 8
        for (int d = 0; d < EE; d += 2) {
            a0 += pe[p][d]     * wrow[d];
            a1 += pe[p][d + 1] * wrow[d + 1];
        }
        out[(size_t)(b * PP + p) * EE + tid] = bn + a0 + a1;
    }
}

// ---------------------------------------------------------------------------
extern "C" void kernel_launch(void* const* d_in, const int* in_sizes, int n_in,
                              void* d_out, int out_size)
{
    const float* x    = (const float*)d_in[0];
    const float* w_in = (const float*)d_in[1];
    const float* b_in = (const float*)d_in[2];
    const float* w_q  = (const float*)d_in[3];
    const float* b_q  = (const float*)d_in[4];
    const float* w_k  = (const float*)d_in[5];
    const float* b_k  = (const float*)d_in[6];
    const float* w_v  = (const float*)d_in[7];
    const float* b_v  = (const float*)d_in[8];
    const float* w_o  = (const float*)d_in[9];
    const float* b_o  = (const float*)d_in[10];
    const float* w_bd = (const float*)d_in[11];
    const float* b_bd = (const float*)d_in[12];
    const float* w_pr = (const float*)d_in[13];
    const float* b_pr = (const float*)d_in[14];
    float* out = (float*)d_out;

    float *ph, *pq, *pk, *pv;
    cudaGetSymbolAddress((void**)&ph, g_h);
    cudaGetSymbolAddress((void**)&pq, g_q);
    cudaGetSymbolAddress((void**)&pk, g_k);
    cudaGetSymbolAddress((void**)&pv, g_v);

    weff_kernel<<<1, 256>>>(w_o, w_bd, b_o, b_bd);

    dim3 ggrid(BT / 64, EE / 64);
    gemm256<<<ggrid, 256>>>(x,  w_in, b_in, ph, 0);
    gemm256<<<ggrid, 256>>>(ph, w_q,  b_q,  pq, 1);
    gemm256<<<ggrid, 256>>>(ph, w_k,  b_k,  pk, 1);
    gemm256<<<ggrid, 256>>>(ph, w_v,  b_v,  pv, 1);

    attn_kernel<<<dim3(TT / 64, BB * HH), 256>>>(pq, pk, pv, nullptr);

    bs_kernel<<<BT / 8, 256>>>();

    finalize_kernel<<<BB, 256>>>(w_pr, b_pr, out);
}

// round 3
// speedup vs baseline: 1.8514x; 1.8514x over previous
#include <cuda_runtime.h>
#include <cuda_fp16.h>
#include <math.h>
#include <stdint.h>

// Problem constants
#define BB   8
#define TT   2048
#define EE   256
#define HH   4
#define HD   64
#define PP   8
#define BT   (BB*TT)          // 16384
#define NBH  (BB*HH)          // 32

// ---------------- scratch (device globals; no allocation allowed) -----------
__device__ float g_h[BT*EE];
__device__ float g_ao[BT*EE];  // [B][T][E]
__device__ float g_bs[BT];
__device__ float g_weff[EE+1]; // w_eff[256] + b_eff
// fp16 hi/lo splits, [bh][t][64]
__device__ __half g_qh[NBH*TT*HD];
__device__ __half g_ql[NBH*TT*HD];
__device__ __half g_kh[NBH*TT*HD];
__device__ __half g_kl[NBH*TT*HD];
__device__ __half g_vh[NBH*TT*HD];
__device__ __half g_vl[NBH*TT*HD];

// ============================ warp-mma helpers ==============================
__device__ __forceinline__ uint32_t smem_u32(const void* p) {
    uint32_t a;
    asm("{ .reg .u64 tmp; cvta.to.shared.u64 tmp, %1; cvt.u32.u64 %0, tmp; }"
        : "=r"(a) : "l"(p));
    return a;
}

__device__ __forceinline__ void ldmatrix_x4(uint32_t* r, uint32_t addr) {
    asm volatile("ldmatrix.sync.aligned.m8n8.x4.shared.b16 {%0,%1,%2,%3}, [%4];"
                 : "=r"(r[0]), "=r"(r[1]), "=r"(r[2]), "=r"(r[3]) : "r"(addr));
}
__device__ __forceinline__ void ldmatrix_x2(uint32_t* r, uint32_t addr) {
    asm volatile("ldmatrix.sync.aligned.m8n8.x2.shared.b16 {%0,%1}, [%2];"
                 : "=r"(r[0]), "=r"(r[1]) : "r"(addr));
}
__device__ __forceinline__ void ldmatrix_x2_trans(uint32_t* r, uint32_t addr) {
    asm volatile("ldmatrix.sync.aligned.m8n8.x2.trans.shared.b16 {%0,%1}, [%2];"
                 : "=r"(r[0]), "=r"(r[1]) : "r"(addr));
}
__device__ __forceinline__ void mma16816(float* d, const uint32_t* a, const uint32_t* b) {
    asm volatile(
        "mma.sync.aligned.m16n8k16.row.col.f32.f16.f16.f32 "
        "{%0,%1,%2,%3}, {%4,%5,%6,%7}, {%8,%9}, {%0,%1,%2,%3};"
        : "+f"(d[0]), "+f"(d[1]), "+f"(d[2]), "+f"(d[3])
        : "r"(a[0]), "r"(a[1]), "r"(a[2]), "r"(a[3]), "r"(b[0]), "r"(b[1]));
}

__device__ __forceinline__ uint32_t pack_half2(__half lo, __half hi) {
    return (uint32_t)__half_as_ushort(lo) | ((uint32_t)__half_as_ushort(hi) << 16);
}

// ---------------------------------------------------------------------------
// w_eff[j] = sum_i w_bd[i] * w_o[i][j];  b_eff = sum_i w_bd[i]*b_o[i] + b_bd
__global__ void weff_kernel(const float* __restrict__ w_o,
                            const float* __restrict__ w_bd,
                            const float* __restrict__ b_o,
                            const float* __restrict__ b_bd)
{
    int j = threadIdx.x;
    float s = 0.f;
    for (int i = 0; i < EE; i++) s += w_bd[i] * w_o[i*EE + j];
    g_weff[j] = s;
    if (j == 0) {
        float bb = b_bd[0];
        for (int i = 0; i < EE; i++) bb += w_bd[i] * b_o[i];
        g_weff[EE] = bb;
    }
}

// ---------------------------------------------------------------------------
// out[m][n] = sum_k A[m][k]*W[n][k] + bias[n]
// mode 0: fp32 row-major to outf.
// mode 1: q -> fp16 hi/lo at [bh][t][d], pre-scaled by 0.125
// mode 2: k/v -> fp16 hi/lo at [bh][t][d]
__global__ __launch_bounds__(256) void gemm256(const float* __restrict__ A,
                                               const float* __restrict__ W,
                                               const float* __restrict__ bias,
                                               float* __restrict__ outf,
                                               __half* __restrict__ oh,
                                               __half* __restrict__ ol,
                                               int mode)
{
    __shared__ float As[16][64];   // [k][row]
    __shared__ float Ws[16][64];   // [k][col]
    const int m0 = blockIdx.x * 64;
    const int n0 = blockIdx.y * 64;
    const int tid = threadIdx.x;
    const int ty = tid >> 4, tx = tid & 15;
    const int lr = tid >> 2;              // 0..63
    const int lc = (tid & 3) << 2;        // 0,4,8,12

    float acc[4][4];
#pragma unroll
    for (int i = 0; i < 4; i++)
#pragma unroll
        for (int j = 0; j < 4; j++) acc[i][j] = 0.f;

    const float* Ap = A + (size_t)(m0 + lr) * EE + lc;
    const float* Wp = W + (size_t)(n0 + lr) * EE + lc;

    for (int k0 = 0; k0 < EE; k0 += 16) {
        float4 av = *(const float4*)(Ap + k0);
        float4 wv = *(const float4*)(Wp + k0);
        __syncthreads();
        As[lc+0][lr] = av.x; As[lc+1][lr] = av.y; As[lc+2][lr] = av.z; As[lc+3][lr] = av.w;
        Ws[lc+0][lr] = wv.x; Ws[lc+1][lr] = wv.y; Ws[lc+2][lr] = wv.z; Ws[lc+3][lr] = wv.w;
        __syncthreads();
#pragma unroll
        for (int kk = 0; kk < 16; kk++) {
            float4 a4 = *(const float4*)&As[kk][ty << 2];
            float4 w4 = *(const float4*)&Ws[kk][tx << 2];
            float ar[4] = {a4.x, a4.y, a4.z, a4.w};
            float wr[4] = {w4.x, w4.y, w4.z, w4.w};
#pragma unroll
            for (int i = 0; i < 4; i++)
#pragma unroll
                for (int j = 0; j < 4; j++) acc[i][j] += ar[i] * wr[j];
        }
    }

    float bn[4];
#pragma unroll
    for (int j = 0; j < 4; j++) bn[j] = bias[n0 + (tx << 2) + j];

    if (mode == 0) {
#pragma unroll
        for (int i = 0; i < 4; i++) {
            int row = m0 + (ty << 2) + i;
#pragma unroll
            for (int j = 0; j < 4; j++)
                outf[(size_t)row * EE + n0 + (tx << 2) + j] = acc[i][j] + bn[j];
        }
    } else {
        const float scale = (mode == 1) ? 0.125f : 1.0f;
#pragma unroll
        for (int i = 0; i < 4; i++) {
            int row = m0 + (ty << 2) + i;
            int b = row >> 11, t = row & (TT - 1);
#pragma unroll
            for (int j = 0; j < 4; j++) {
                int n = n0 + (tx << 2) + j;
                int hh = n >> 6, d = n & 63;
                float val = (acc[i][j] + bn[j]) * scale;
                __half vh = __float2half_rn(val);
                __half vl = __float2half_rn(val - __half2float(vh));
                size_t idx = ((size_t)((b * HH + hh) * TT + t)) * HD + d;
                oh[idx] = vh;
                ol[idx] = vl;
            }
        }
    }
}

// ---------------------------------------------------------------------------
// Flash attention via mma.sync m16n8k16 fp16, 3-MMA hi/lo split (fp32-accurate).
// CTA: 128 threads (4 warps), 64 query rows; warp w owns rows [16w,16w+16).
// KV tiles of 64. No online rescaling (scores bounded): p = exp(s), O/l at end.
struct AttnSmem {
    __half kh[64][72];
    __half kl[64][72];
    __half vh[64][72];
    __half vl[64][72];
};

__global__ __launch_bounds__(128) void attn_mma()
{
    __shared__ AttnSmem sm;
    const int tid = threadIdx.x;
    const int wid = tid >> 5;
    const int lane = tid & 31;
    const int bh = blockIdx.y;
    const int qt0 = blockIdx.x * 64;
    const int b = bh >> 2, hh = bh & 3;
    const int g = lane >> 2, t4 = lane & 3;

    // ---- stage Q (hi/lo) into kh/kl, extract A-fragments ----
    {
        const uint4* Qh = (const uint4*)(g_qh + ((size_t)bh * TT + qt0) * HD);
        const uint4* Ql = (const uint4*)(g_ql + ((size_t)bh * TT + qt0) * HD);
#pragma unroll
        for (int i = tid; i < 512; i += 128) {
            int r = i >> 3, c8 = i & 7;
            *(uint4*)&sm.kh[r][c8 * 8] = Qh[i];
            *(uint4*)&sm.kl[r][c8 * 8] = Ql[i];
        }
    }
    __syncthreads();

    uint32_t qfh[4][4], qfl[4][4];
    {
        int arow = 16 * wid + (lane & 7) + ((lane & 8) ? 8 : 0);
        int acolsel = (lane & 16) ? 8 : 0;
#pragma unroll
        for (int kc = 0; kc < 4; kc++) {
            ldmatrix_x4(qfh[kc], smem_u32(&sm.kh[arow][kc * 16 + acolsel]));
            ldmatrix_x4(qfl[kc], smem_u32(&sm.kl[arow][kc * 16 + acolsel]));
        }
    }
    __syncthreads();

    float O[8][4];
#pragma unroll
    for (int i = 0; i < 8; i++)
#pragma unroll
        for (int j = 0; j < 4; j++) O[i][j] = 0.f;
    float lacc0 = 0.f, lacc8 = 0.f;

    const int brow = lane & 7;
    const int bcolsel = (lane & 8) ? 8 : 0;
    const int vrow = lane & 15;

    for (int kt = 0; kt < TT / 64; kt++) {
        // ---- load K/V hi+lo tiles ----
        {
            const size_t base = ((size_t)bh * TT + kt * 64) * HD;
            const uint4* Kh = (const uint4*)(g_kh + base);
            const uint4* Kl = (const uint4*)(g_kl + base);
            const uint4* Vh = (const uint4*)(g_vh + base);
            const uint4* Vl = (const uint4*)(g_vl + base);
#pragma unroll
            for (int i = tid; i < 512; i += 128) {
                int r = i >> 3, c8 = i & 7;
                *(uint4*)&sm.kh[r][c8 * 8] = Kh[i];
                *(uint4*)&sm.kl[r][c8 * 8] = Kl[i];
                *(uint4*)&sm.vh[r][c8 * 8] = Vh[i];
                *(uint4*)&sm.vl[r][c8 * 8] = Vl[i];
            }
        }
        __syncthreads();

        // ---- S = Q K^T  (16q x 64kv per warp), 3-way split ----
        float S[8][4];
#pragma unroll
        for (int i = 0; i < 8; i++)
#pragma unroll
            for (int j = 0; j < 4; j++) S[i][j] = 0.f;

#pragma unroll
        for (int kc = 0; kc < 4; kc++) {
#pragma unroll
            for (int nb = 0; nb < 8; nb++) {
                uint32_t bfh[2], bfl[2];
                ldmatrix_x2(bfh, smem_u32(&sm.kh[8 * nb + brow][16 * kc + bcolsel]));
                ldmatrix_x2(bfl, smem_u32(&sm.kl[8 * nb + brow][16 * kc + bcolsel]));
                mma16816(S[nb], qfh[kc], bfh);
                mma16816(S[nb], qfh[kc], bfl);
                mma16816(S[nb], qfl[kc], bfh);
            }
        }

        // ---- p = exp(s); accumulate l; build P fragments (hi/lo fp16) ----
        uint32_t pfh[4][4], pfl[4][4];
#pragma unroll
        for (int nb = 0; nb < 8; nb++) {
            float p0 = __expf(S[nb][0]);
            float p1 = __expf(S[nb][1]);
            float p2 = __expf(S[nb][2]);
            float p3 = __expf(S[nb][3]);
            lacc0 += p0 + p1;
            lacc8 += p2 + p3;
            __half h0 = __float2half_rn(p0), h1 = __float2half_rn(p1);
            __half h2 = __float2half_rn(p2), h3 = __float2half_rn(p3);
            __half e0 = __float2half_rn(p0 - __half2float(h0));
            __half e1 = __float2half_rn(p1 - __half2float(h1));
            __half e2 = __float2half_rn(p2 - __half2float(h2));
            __half e3 = __float2half_rn(p3 - __half2float(h3));
            int c = nb >> 1, odd = nb & 1;
            pfh[c][2 * odd + 0] = pack_half2(h0, h1);
            pfh[c][2 * odd + 1] = pack_half2(h2, h3);
            pfl[c][2 * odd + 0] = pack_half2(e0, e1);
            pfl[c][2 * odd + 1] = pack_half2(e2, e3);
        }

        // ---- O += P V, 3-way split ----
#pragma unroll
        for (int db = 0; db < 8; db++) {
#pragma unroll
            for (int c = 0; c < 4; c++) {
                uint32_t bvh[2], bvl[2];
                ldmatrix_x2_trans(bvh, smem_u32(&sm.vh[16 * c + vrow][8 * db]));
                ldmatrix_x2_trans(bvl, smem_u32(&sm.vl[16 * c + vrow][8 * db]));
                mma16816(O[db], pfh[c], bvh);
                mma16816(O[db], pfh[c], bvl);
                mma16816(O[db], pfl[c], bvh);
            }
        }
        __syncthreads();
    }

    // reduce l across the 4 lanes of each row group
#pragma unroll
    for (int m = 1; m <= 2; m <<= 1) {
        lacc0 += __shfl_xor_sync(0xffffffffu, lacc0, m);
        lacc8 += __shfl_xor_sync(0xffffffffu, lacc8, m);
    }
    const float inv0 = 1.0f / lacc0;
    const float inv8 = 1.0f / lacc8;

    float* dst = g_ao + ((size_t)(b * TT) + qt0 + 16 * wid) * EE + hh * HD;
#pragma unroll
    for (int db = 0; db < 8; db++) {
        float2 v0 = make_float2(O[db][0] * inv0, O[db][1] * inv0);
        float2 v1 = make_float2(O[db][2] * inv8, O[db][3] * inv8);
        *(float2*)(dst + (size_t)g * EE + 8 * db + 2 * t4) = v0;
        *(float2*)(dst + (size_t)(g + 8) * EE + 8 * db + 2 * t4) = v1;
    }
}

// ---------------------------------------------------------------------------
// bs[t] = sigmoid(ao[t]·w_eff + b_eff). One warp per token.
__global__ __launch_bounds__(256) void bs_kernel()
{
    int t = blockIdx.x * 8 + (threadIdx.x >> 5);
    int lane = threadIdx.x & 31;
    const float* row = g_ao + (size_t)t * EE;
    float z = 0.f;
#pragma unroll
    for (int j = lane; j < EE; j += 32) z += row[j] * g_weff[j];
#pragma unroll
    for (int msk = 16; msk >= 1; msk >>= 1)
        z += __shfl_xor_sync(0xffffffffu, z, msk);
    if (lane == 0) {
        z += g_weff[EE];
        g_bs[t] = 1.0f / (1.0f + expf(-z));
    }
}

// ---------------------------------------------------------------------------
// Per batch: fp64 cumsum -> pid -> contiguous-range segment means -> w_pr proj
__global__ __launch_bounds__(256) void finalize_kernel(const float* __restrict__ w_pr,
                                                       const float* __restrict__ b_pr,
                                                       float* __restrict__ out)
{
    __shared__ float  sc[TT];
    __shared__ double sd[TT];
    __shared__ double part[256];
    __shared__ unsigned char pids[TT];
    __shared__ int starts[PP + 1];
    __shared__ float pe[PP][EE];

    const int b = blockIdx.x;
    const int tid = threadIdx.x;

    for (int t = tid; t < TT; t += 256) sc[t] = g_bs[b * TT + t];
    __syncthreads();

    // fp64 cumsum: per-thread segment of 8, then serial scan of 256 partials
    {
        double s = 0.0;
#pragma unroll
        for (int i = 0; i < 8; i++) s += (double)sc[tid * 8 + i];
        part[tid] = s;
    }
    __syncthreads();
    if (tid == 0) {
        double run = 0.0;
        for (int i = 0; i < 256; i++) { double v = part[i]; part[i] = run; run += v; }
    }
    __syncthreads();
    {
        double c = part[tid];
#pragma unroll
        for (int i = 0; i < 8; i++) { c += (double)sc[tid * 8 + i]; sd[tid * 8 + i] = c; }
    }
    __syncthreads();

    double total = sd[TT - 1];
    double inv = 1.0 / fmax(total, 1e-6);
    for (int t = tid; t < TT; t += 256) {
        int p = (int)(sd[t] * inv * (double)PP);
        pids[t] = (unsigned char)(p > PP - 1 ? PP - 1 : p);
    }
    __syncthreads();

    if (tid == 0) {
        int cur = pids[0];
        for (int p = 0; p <= cur; p++) starts[p] = 0;
        for (int t = 1; t < TT; t++) {
            int p = pids[t];
            while (cur < p) starts[++cur] = t;
        }
        while (cur < PP) starts[++cur] = TT;
    }
    __syncthreads();

    // segment means; thread owns dim d = tid
    const float* hb = g_h + (size_t)b * TT * EE;
    for (int p = 0; p < PP; p++) {
        int s0 = starts[p], s1 = starts[p + 1];
        float a0 = 0.f, a1 = 0.f;
        int t = s0;
        for (; t + 1 < s1; t += 2) {
            a0 += hb[(size_t)t * EE + tid];
            a1 += hb[(size_t)(t + 1) * EE + tid];
        }
        if (t < s1) a0 += hb[(size_t)t * EE + tid];
        float cnt = (float)(s1 - s0);
        pe[p][tid] = (a0 + a1) / fmaxf(cnt, 1.0f);
    }
    __syncthreads();

    // out[b][p][n] = pe[p]·w_pr[n] + b_pr[n]; thread owns n = tid
    float bn = b_pr[tid];
    const float* wrow = w_pr + (size_t)tid * EE;
    for (int p = 0; p < PP; p++) {
        float a0 = 0.f, a1 = 0.f;
#pragma unroll 8
        for (int d = 0; d < EE; d += 2) {
            a0 += pe[p][d]     * wrow[d];
            a1 += pe[p][d + 1] * wrow[d + 1];
        }
        out[(size_t)(b * PP + p) * EE + tid] = bn + a0 + a1;
    }
}

// ---------------------------------------------------------------------------
extern "C" void kernel_launch(void* const* d_in, const int* in_sizes, int n_in,
                              void* d_out, int out_size)
{
    const float* x    = (const float*)d_in[0];
    const float* w_in = (const float*)d_in[1];
    const float* b_in = (const float*)d_in[2];
    const float* w_q  = (const float*)d_in[3];
    const float* b_q  = (const float*)d_in[4];
    const float* w_k  = (const float*)d_in[5];
    const float* b_k  = (const float*)d_in[6];
    const float* w_v  = (const float*)d_in[7];
    const float* b_v  = (const float*)d_in[8];
    const float* w_o  = (const float*)d_in[9];
    const float* b_o  = (const float*)d_in[10];
    const float* w_bd = (const float*)d_in[11];
    const float* b_bd = (const float*)d_in[12];
    const float* w_pr = (const float*)d_in[13];
    const float* b_pr = (const float*)d_in[14];
    float* out = (float*)d_out;

    float *ph;
    __half *pqh, *pql, *pkh, *pkl, *pvh, *pvl;
    cudaGetSymbolAddress((void**)&ph,  g_h);
    cudaGetSymbolAddress((void**)&pqh, g_qh);
    cudaGetSymbolAddress((void**)&pql, g_ql);
    cudaGetSymbolAddress((void**)&pkh, g_kh);
    cudaGetSymbolAddress((void**)&pkl, g_kl);
    cudaGetSymbolAddress((void**)&pvh, g_vh);
    cudaGetSymbolAddress((void**)&pvl, g_vl);

    weff_kernel<<<1, 256>>>(w_o, w_bd, b_o, b_bd);

    dim3 ggrid(BT / 64, EE / 64);
    gemm256<<<ggrid, 256>>>(x,  w_in, b_in, ph, nullptr, nullptr, 0);
    gemm256<<<ggrid, 256>>>(ph, w_q,  b_q,  nullptr, pqh, pql, 1);
    gemm256<<<ggrid, 256>>>(ph, w_k,  b_k,  nullptr, pkh, pkl, 2);
    gemm256<<<ggrid, 256>>>(ph, w_v,  b_v,  nullptr, pvh, pvl, 2);

    attn_mma<<<dim3(TT / 64, NBH), 128>>>();

    bs_kernel<<<BT / 8, 256>>>();

    finalize_kernel<<<BB, 256>>>(w_pr, b_pr, out);
}

// round 6
// speedup vs baseline: 2.0971x; 1.1327x over previous
#include <cuda_runtime.h>
#include <cuda_fp16.h>
#include <math.h>
#include <stdint.h>

// Problem constants
#define BB   8
#define TT   2048
#define EE   256
#define HH   4
#define HD   64
#define PP   8
#define BT   (BB*TT)          // 16384
#define NBH  (BB*HH)          // 32

// ---------------- scratch (device globals; no allocation allowed) -----------
__device__ float g_h[BT*EE];
__device__ float g_bs[BT];
__device__ float g_weff[EE+1];       // w_eff[256] + b_eff
__device__ float g_zp[HH][BT];       // per-head boundary partials
__device__ float g_chs[BB][32][EE];  // 64-token chunk sums of h
// fp16 hi/lo splits
__device__ __half g_xh[BT*EE], g_xl[BT*EE];
__device__ __half g_hh[BT*EE], g_hl[BT*EE];
__device__ __half g_wsh[4][EE*EE], g_wsl[4][EE*EE];   // w_in, w_q, w_k, w_v
// [bh][t][64] layouts
__device__ __half g_qh[NBH*TT*HD], g_ql[NBH*TT*HD];
__device__ __half g_kh[NBH*TT*HD], g_kl[NBH*TT*HD];
__device__ __half g_vh[NBH*TT*HD], g_vl[NBH*TT*HD];

// ============================ warp-mma helpers ==============================
__device__ __forceinline__ uint32_t smem_u32(const void* p) {
    uint32_t a;
    asm("{ .reg .u64 tmp; cvta.to.shared.u64 tmp, %1; cvt.u32.u64 %0, tmp; }"
        : "=r"(a) : "l"(p));
    return a;
}
__device__ __forceinline__ void ldmatrix_x4(uint32_t* r, uint32_t addr) {
    asm volatile("ldmatrix.sync.aligned.m8n8.x4.shared.b16 {%0,%1,%2,%3}, [%4];"
                 : "=r"(r[0]), "=r"(r[1]), "=r"(r[2]), "=r"(r[3]) : "r"(addr));
}
__device__ __forceinline__ void ldmatrix_x2(uint32_t* r, uint32_t addr) {
    asm volatile("ldmatrix.sync.aligned.m8n8.x2.shared.b16 {%0,%1}, [%2];"
                 : "=r"(r[0]), "=r"(r[1]) : "r"(addr));
}
__device__ __forceinline__ void ldmatrix_x2_trans(uint32_t* r, uint32_t addr) {
    asm volatile("ldmatrix.sync.aligned.m8n8.x2.trans.shared.b16 {%0,%1}, [%2];"
                 : "=r"(r[0]), "=r"(r[1]) : "r"(addr));
}
__device__ __forceinline__ void mma16816(float* d, const uint32_t* a, const uint32_t* b) {
    asm volatile(
        "mma.sync.aligned.m16n8k16.row.col.f32.f16.f16.f32 "
        "{%0,%1,%2,%3}, {%4,%5,%6,%7}, {%8,%9}, {%0,%1,%2,%3};"
        : "+f"(d[0]), "+f"(d[1]), "+f"(d[2]), "+f"(d[3])
        : "r"(a[0]), "r"(a[1]), "r"(a[2]), "r"(a[3]), "r"(b[0]), "r"(b[1]));
}
__device__ __forceinline__ uint32_t pack_half2(__half lo, __half hi) {
    return (uint32_t)__half_as_ushort(lo) | ((uint32_t)__half_as_ushort(hi) << 16);
}

// ---------------------------------------------------------------------------
// w_eff[j] = sum_i w_bd[i] * w_o[i][j];  b_eff = sum_i w_bd[i]*b_o[i] + b_bd
__global__ void weff_kernel(const float* __restrict__ w_o,
                            const float* __restrict__ w_bd,
                            const float* __restrict__ b_o,
                            const float* __restrict__ b_bd)
{
    int j = threadIdx.x;
    float s = 0.f;
    for (int i = 0; i < EE; i++) s += w_bd[i] * w_o[i*EE + j];
    g_weff[j] = s;
    if (j == 0) {
        float bb = b_bd[0];
        for (int i = 0; i < EE; i++) bb += w_bd[i] * b_o[i];
        g_weff[EE] = bb;
    }
}

// ---------------------------------------------------------------------------
// Generic fp32 -> fp16 hi/lo split (float4 granularity).
__global__ __launch_bounds__(256) void split_kernel(const float* __restrict__ src,
                                                    __half* __restrict__ dh,
                                                    __half* __restrict__ dl,
                                                    int n4)
{
    int i = blockIdx.x * 256 + threadIdx.x;
    if (i >= n4) return;
    float4 v = ((const float4*)src)[i];
    __half h0 = __float2half_rn(v.x), h1 = __float2half_rn(v.y);
    __half h2 = __float2half_rn(v.z), h3 = __float2half_rn(v.w);
    __half l0 = __float2half_rn(v.x - __half2float(h0));
    __half l1 = __float2half_rn(v.y - __half2float(h1));
    __half l2 = __float2half_rn(v.z - __half2float(h2));
    __half l3 = __float2half_rn(v.w - __half2float(h3));
    ((uint2*)dh)[i] = make_uint2(pack_half2(h0, h1), pack_half2(h2, h3));
    ((uint2*)dl)[i] = make_uint2(pack_half2(l0, l1), pack_half2(l2, l3));
}

// ---------------------------------------------------------------------------
// Tensor-core GEMM: C[m][n] = sum_k A[m][k]*W[n][k] + bias[n], fp16 3-MMA split.
// CTA: 128 threads (4 warps), tile 64(m) x 64(n); warp w owns rows [16w,16w+16).
// Grid: (M/64, 256/64).
// mode 0: write fp32 to outf AND hi/lo split to oh/ol (row-major [m][256]).
// mode 1: q -> oh/ol at [bh][t][d], scaled by 0.125.  mode 2: k/v -> oh/ol.
__global__ __launch_bounds__(128) void gemm_tc(const __half* __restrict__ Ah,
                                               const __half* __restrict__ Al,
                                               const __half* __restrict__ Wh,
                                               const __half* __restrict__ Wl,
                                               const float* __restrict__ bias,
                                               float* __restrict__ outf,
                                               __half* __restrict__ oh,
                                               __half* __restrict__ ol,
                                               int mode)
{
    __shared__ __half Ash[64][72], Asl[64][72], Wsh[64][72], Wsl[64][72];
    const int m0 = blockIdx.x * 64;
    const int n0 = blockIdx.y * 64;
    const int tid = threadIdx.x;
    const int wid = tid >> 5;
    const int lane = tid & 31;
    const int g = lane >> 2, t4 = lane & 3;

    float acc[8][4];
#pragma unroll
    for (int i = 0; i < 8; i++)
#pragma unroll
        for (int j = 0; j < 4; j++) acc[i][j] = 0.f;

    const int arow = 16 * wid + (lane & 15);
    const int asel = (lane & 16) ? 8 : 0;
    const int brow = lane & 7;
    const int bsel = (lane & 8) ? 8 : 0;

    for (int kc0 = 0; kc0 < EE; kc0 += 64) {
        if (kc0) __syncthreads();
#pragma unroll
        for (int j = 0; j < 4; j++) {
            int i = tid + j * 128;            // 0..511
            int r = i >> 3, c = (i & 7) * 8;
            *(uint4*)&Ash[r][c] = *(const uint4*)&Ah[(size_t)(m0 + r) * EE + kc0 + c];
            *(uint4*)&Asl[r][c] = *(const uint4*)&Al[(size_t)(m0 + r) * EE + kc0 + c];
            *(uint4*)&Wsh[r][c] = *(const uint4*)&Wh[(size_t)(n0 + r) * EE + kc0 + c];
            *(uint4*)&Wsl[r][c] = *(const uint4*)&Wl[(size_t)(n0 + r) * EE + kc0 + c];
        }
        __syncthreads();

        uint32_t afh[4][4], afl[4][4];
#pragma unroll
        for (int kc = 0; kc < 4; kc++) {
            ldmatrix_x4(afh[kc], smem_u32(&Ash[arow][kc * 16 + asel]));
            ldmatrix_x4(afl[kc], smem_u32(&Asl[arow][kc * 16 + asel]));
        }
#pragma unroll
        for (int kc = 0; kc < 4; kc++) {
#pragma unroll
            for (int nb = 0; nb < 8; nb++) {
                uint32_t bh2[2], bl2[2];
                ldmatrix_x2(bh2, smem_u32(&Wsh[8 * nb + brow][kc * 16 + bsel]));
                ldmatrix_x2(bl2, smem_u32(&Wsl[8 * nb + brow][kc * 16 + bsel]));
                mma16816(acc[nb], afh[kc], bh2);
                mma16816(acc[nb], afh[kc], bl2);
                mma16816(acc[nb], afl[kc], bh2);
            }
        }
    }

    // epilogue
    const int r0 = m0 + 16 * wid + g;
    const int r1 = r0 + 8;
    const float scale = (mode == 1) ? 0.125f : 1.0f;
#pragma unroll
    for (int nb = 0; nb < 8; nb++) {
        int c0 = n0 + 8 * nb + 2 * t4;
        float bx = bias[c0], by = bias[c0 + 1];
        float v00 = acc[nb][0] + bx, v01 = acc[nb][1] + by;
        float v10 = acc[nb][2] + bx, v11 = acc[nb][3] + by;
        if (mode == 0) {
            *(float2*)&outf[(size_t)r0 * EE + c0] = make_float2(v00, v01);
            *(float2*)&outf[(size_t)r1 * EE + c0] = make_float2(v10, v11);
            __half h00 = __float2half_rn(v00), h01 = __float2half_rn(v01);
            __half h10 = __float2half_rn(v10), h11 = __float2half_rn(v11);
            *(uint32_t*)&oh[(size_t)r0 * EE + c0] = pack_half2(h00, h01);
            *(uint32_t*)&oh[(size_t)r1 * EE + c0] = pack_half2(h10, h11);
            *(uint32_t*)&ol[(size_t)r0 * EE + c0] =
                pack_half2(__float2half_rn(v00 - __half2float(h00)),
                           __float2half_rn(v01 - __half2float(h01)));
            *(uint32_t*)&ol[(size_t)r1 * EE + c0] =
                pack_half2(__float2half_rn(v10 - __half2float(h10)),
                           __float2half_rn(v11 - __half2float(h11)));
        } else {
            v00 *= scale; v01 *= scale; v10 *= scale; v11 *= scale;
            int hh = c0 >> 6, d = c0 & 63;
            int b = r0 >> 11, t0n = r0 & (TT - 1);
            size_t base = ((size_t)((b * HH + hh) * TT)) * HD + d;
            size_t i0 = base + (size_t)t0n * HD;
            size_t i1 = base + (size_t)(t0n + 8) * HD;
            __half h00 = __float2half_rn(v00), h01 = __float2half_rn(v01);
            __half h10 = __float2half_rn(v10), h11 = __float2half_rn(v11);
            *(uint32_t*)&oh[i0] = pack_half2(h00, h01);
            *(uint32_t*)&oh[i1] = pack_half2(h10, h11);
            *(uint32_t*)&ol[i0] =
                pack_half2(__float2half_rn(v00 - __half2float(h00)),
                           __float2half_rn(v01 - __half2float(h01)));
            *(uint32_t*)&ol[i1] =
                pack_half2(__float2half_rn(v10 - __half2float(h10)),
                           __float2half_rn(v11 - __half2float(h11)));
        }
    }
}

// ---------------------------------------------------------------------------
// 64-token chunk sums of h: g_chs[b][c][d] = sum_{t in chunk} h[b][t][d]
__global__ __launch_bounds__(256) void chs_kernel()
{
    int b = blockIdx.x, c = blockIdx.y, d = threadIdx.x;
    const float* p = g_h + ((size_t)b * TT + c * 64) * EE + d;
    float s = 0.f;
#pragma unroll 8
    for (int i = 0; i < 64; i++) s += p[(size_t)i * EE];
    g_chs[b][c][d] = s;
}

// ---------------------------------------------------------------------------
// Flash attention via mma.sync m16n8k16 fp16, 3-MMA hi/lo split (fp32-accurate).
// CTA: 128 threads (4 warps), 64 query rows; warp w owns rows [16w,16w+16).
// Epilogue: per-head boundary partial z = (O . w_eff_slice) / l  -> g_zp.
struct AttnSmem {
    __half kh[64][72];
    __half kl[64][72];
    __half vh[64][72];
    __half vl[64][72];
};

__global__ __launch_bounds__(128) void attn_mma()
{
    __shared__ AttnSmem sm;
    const int tid = threadIdx.x;
    const int wid = tid >> 5;
    const int lane = tid & 31;
    const int bh = blockIdx.y;
    const int qt0 = blockIdx.x * 64;
    const int b = bh >> 2, hh = bh & 3;
    const int g = lane >> 2, t4 = lane & 3;

    // ---- stage Q (hi/lo) into kh/kl, extract A-fragments ----
    {
        const uint4* Qh = (const uint4*)(g_qh + ((size_t)bh * TT + qt0) * HD);
        const uint4* Ql = (const uint4*)(g_ql + ((size_t)bh * TT + qt0) * HD);
#pragma unroll
        for (int i = tid; i < 512; i += 128) {
            int r = i >> 3, c8 = i & 7;
            *(uint4*)&sm.kh[r][c8 * 8] = Qh[i];
            *(uint4*)&sm.kl[r][c8 * 8] = Ql[i];
        }
    }
    __syncthreads();

    uint32_t qfh[4][4], qfl[4][4];
    {
        int arow = 16 * wid + (lane & 15);
        int acolsel = (lane & 16) ? 8 : 0;
#pragma unroll
        for (int kc = 0; kc < 4; kc++) {
            ldmatrix_x4(qfh[kc], smem_u32(&sm.kh[arow][kc * 16 + acolsel]));
            ldmatrix_x4(qfl[kc], smem_u32(&sm.kl[arow][kc * 16 + acolsel]));
        }
    }
    __syncthreads();

    float O[8][4];
#pragma unroll
    for (int i = 0; i < 8; i++)
#pragma unroll
        for (int j = 0; j < 4; j++) O[i][j] = 0.f;
    float lacc0 = 0.f, lacc8 = 0.f;

    const int brow = lane & 7;
    const int bcolsel = (lane & 8) ? 8 : 0;
    const int vrow = lane & 15;

    for (int kt = 0; kt < TT / 64; kt++) {
        {
            const size_t base = ((size_t)bh * TT + kt * 64) * HD;
            const uint4* Kh = (const uint4*)(g_kh + base);
            const uint4* Kl = (const uint4*)(g_kl + base);
            const uint4* Vh = (const uint4*)(g_vh + base);
            const uint4* Vl = (const uint4*)(g_vl + base);
#pragma unroll
            for (int i = tid; i < 512; i += 128) {
                int r = i >> 3, c8 = i & 7;
                *(uint4*)&sm.kh[r][c8 * 8] = Kh[i];
                *(uint4*)&sm.kl[r][c8 * 8] = Kl[i];
                *(uint4*)&sm.vh[r][c8 * 8] = Vh[i];
                *(uint4*)&sm.vl[r][c8 * 8] = Vl[i];
            }
        }
        __syncthreads();

        // ---- S = Q K^T, 3-way split ----
        float S[8][4];
#pragma unroll
        for (int i = 0; i < 8; i++)
#pragma unroll
            for (int j = 0; j < 4; j++) S[i][j] = 0.f;
#pragma unroll
        for (int kc = 0; kc < 4; kc++) {
#pragma unroll
            for (int nb = 0; nb < 8; nb++) {
                uint32_t bfh[2], bfl[2];
                ldmatrix_x2(bfh, smem_u32(&sm.kh[8 * nb + brow][16 * kc + bcolsel]));
                ldmatrix_x2(bfl, smem_u32(&sm.kl[8 * nb + brow][16 * kc + bcolsel]));
                mma16816(S[nb], qfh[kc], bfh);
                mma16816(S[nb], qfh[kc], bfl);
                mma16816(S[nb], qfl[kc], bfh);
            }
        }

        // ---- p = exp(s); accumulate l; build P fragments (hi/lo) ----
        uint32_t pfh[4][4], pfl[4][4];
#pragma unroll
        for (int nb = 0; nb < 8; nb++) {
            float p0 = __expf(S[nb][0]);
            float p1 = __expf(S[nb][1]);
            float p2 = __expf(S[nb][2]);
            float p3 = __expf(S[nb][3]);
            lacc0 += p0 + p1;
            lacc8 += p2 + p3;
            __half h0 = __float2half_rn(p0), h1 = __float2half_rn(p1);
            __half h2 = __float2half_rn(p2), h3 = __float2half_rn(p3);
            __half e0 = __float2half_rn(p0 - __half2float(h0));
            __half e1 = __float2half_rn(p1 - __half2float(h1));
            __half e2 = __float2half_rn(p2 - __half2float(h2));
            __half e3 = __float2half_rn(p3 - __half2float(h3));
            int c = nb >> 1, odd = nb & 1;
            pfh[c][2 * odd + 0] = pack_half2(h0, h1);
            pfh[c][2 * odd + 1] = pack_half2(h2, h3);
            pfl[c][2 * odd + 0] = pack_half2(e0, e1);
            pfl[c][2 * odd + 1] = pack_half2(e2, e3);
        }

        // ---- O += P V, 3-way split ----
#pragma unroll
        for (int db = 0; db < 8; db++) {
#pragma unroll
            for (int c = 0; c < 4; c++) {
                uint32_t bvh[2], bvl[2];
                ldmatrix_x2_trans(bvh, smem_u32(&sm.vh[16 * c + vrow][8 * db]));
                ldmatrix_x2_trans(bvl, smem_u32(&sm.vl[16 * c + vrow][8 * db]));
                mma16816(O[db], pfh[c], bvh);
                mma16816(O[db], pfh[c], bvl);
                mma16816(O[db], pfl[c], bvh);
            }
        }
        __syncthreads();
    }

    // reduce l across the 4 lanes of each row group
#pragma unroll
    for (int m = 1; m <= 2; m <<= 1) {
        lacc0 += __shfl_xor_sync(0xffffffffu, lacc0, m);
        lacc8 += __shfl_xor_sync(0xffffffffu, lacc8, m);
    }
    const float inv0 = 1.0f / lacc0;
    const float inv8 = 1.0f / lacc8;

    // ---- epilogue: z = (O . w_eff_slice) / l per row, reduce quad, store ----
    const float* wep = g_weff + hh * HD;
    float z0 = 0.f, z8 = 0.f;
#pragma unroll
    for (int db = 0; db < 8; db++) {
        float2 we2 = *(const float2*)(wep + 8 * db + 2 * t4);
        z0 += O[db][0] * we2.x + O[db][1] * we2.y;
        z8 += O[db][2] * we2.x + O[db][3] * we2.y;
    }
    z0 *= inv0; z8 *= inv8;
#pragma unroll
    for (int m = 1; m <= 2; m <<= 1) {
        z0 += __shfl_xor_sync(0xffffffffu, z0, m);
        z8 += __shfl_xor_sync(0xffffffffu, z8, m);
    }
    if (t4 == 0) {
        int row = qt0 + 16 * wid + g;
        g_zp[hh][b * TT + row] = z0;
        g_zp[hh][b * TT + row + 8] = z8;
    }
}

// ---------------------------------------------------------------------------
// bs[t] = sigmoid(sum_h zp[h][t] + b_eff)
__global__ __launch_bounds__(256) void zsig_kernel()
{
    int t = blockIdx.x * 256 + threadIdx.x;
    float z = g_zp[0][t] + g_zp[1][t] + g_zp[2][t] + g_zp[3][t] + g_weff[EE];
    g_bs[t] = 1.0f / (1.0f + expf(-z));
}

// ---------------------------------------------------------------------------
// Per batch: fp64 cumsum -> pid -> segment means (chunk sums + edges) -> proj
__global__ __launch_bounds__(256) void finalize_kernel(const float* __restrict__ w_pr,
                                                       const float* __restrict__ b_pr,
                                                       float* __restrict__ out)
{
    __shared__ float  sc[TT];
    __shared__ double sd[TT];
    __shared__ double part[256];
    __shared__ unsigned char pids[TT];
    __shared__ int starts[PP + 1];
    __shared__ float pe[PP][EE];

    const int b = blockIdx.x;
    const int tid = threadIdx.x;

    for (int t = tid; t < TT; t += 256) sc[t] = g_bs[b * TT + t];
    __syncthreads();

    {
        double s = 0.0;
#pragma unroll
        for (int i = 0; i < 8; i++) s += (double)sc[tid * 8 + i];
        part[tid] = s;
    }
    __syncthreads();
    if (tid == 0) {
        double run = 0.0;
        for (int i = 0; i < 256; i++) { double v = part[i]; part[i] = run; run += v; }
    }
    __syncthreads();
    {
        double c = part[tid];
#pragma unroll
        for (int i = 0; i < 8; i++) { c += (double)sc[tid * 8 + i]; sd[tid * 8 + i] = c; }
    }
    __syncthreads();

    double total = sd[TT - 1];
    double inv = 1.0 / fmax(total, 1e-6);
    for (int t = tid; t < TT; t += 256) {
        int p = (int)(sd[t] * inv * (double)PP);
        pids[t] = (unsigned char)(p > PP - 1 ? PP - 1 : p);
    }
    __syncthreads();

    if (tid == 0) {
        int cur = pids[0];
        for (int p = 0; p <= cur; p++) starts[p] = 0;
        for (int t = 1; t < TT; t++) {
            int p = pids[t];
            while (cur < p) starts[++cur] = t;
        }
        while (cur < PP) starts[++cur] = TT;
    }
    __syncthreads();

    // segment means via chunk sums + edge tokens; thread owns dim d = tid
    const float* hb = g_h + (size_t)b * TT * EE;
    for (int p = 0; p < PP; p++) {
        int s0 = starts[p], s1 = starts[p + 1];
        float sum = 0.f;
        int cs = (s0 + 63) >> 6, ce = s1 >> 6;
        if (cs <= ce) {
            for (int c = cs; c < ce; c++) sum += g_chs[b][c][tid];
            for (int t = s0; t < cs * 64; t++) sum += hb[(size_t)t * EE + tid];
            for (int t = ce * 64; t < s1; t++) sum += hb[(size_t)t * EE + tid];
        } else {
            for (int t = s0; t < s1; t++) sum += hb[(size_t)t * EE + tid];
        }
        float cnt = (float)(s1 - s0);
        pe[p][tid] = sum / fmaxf(cnt, 1.0f);
    }
    __syncthreads();

    // out[b][p][n] = pe[p].w_pr[n] + b_pr[n]; thread owns n = tid
    float bn = b_pr[tid];
    const float* wrow = w_pr + (size_t)tid * EE;
    for (int p = 0; p < PP; p++) {
        float a0 = 0.f, a1 = 0.f;
#pragma unroll 8
        for (int d = 0; d < EE; d += 2) {
            a0 += pe[p][d]     * wrow[d];
            a1 += pe[p][d + 1] * wrow[d + 1];
        }
        out[(size_t)(b * PP + p) * EE + tid] = bn + a0 + a1;
    }
}

// ---------------------------------------------------------------------------
extern "C" void kernel_launch(void* const* d_in, const int* in_sizes, int n_in,
                              void* d_out, int out_size)
{
    const float* x    = (const float*)d_in[0];
    const float* w_in = (const float*)d_in[1];
    const float* b_in = (const float*)d_in[2];
    const float* w_q  = (const float*)d_in[3];
    const float* b_q  = (const float*)d_in[4];
    const float* w_k  = (const float*)d_in[5];
    const float* b_k  = (const float*)d_in[6];
    const float* w_v  = (const float*)d_in[7];
    const float* b_v  = (const float*)d_in[8];
    const float* w_o  = (const float*)d_in[9];
    const float* b_o  = (const float*)d_in[10];
    const float* w_bd = (const float*)d_in[11];
    const float* b_bd = (const float*)d_in[12];
    const float* w_pr = (const float*)d_in[13];
    const float* b_pr = (const float*)d_in[14];
    float* out = (float*)d_out;

    float *ph;
    __half *pxh, *pxl, *phh, *phl, *pwh, *pwl;
    __half *pqh, *pql, *pkh, *pkl, *pvh, *pvl;
    cudaGetSymbolAddress((void**)&ph,  g_h);
    cudaGetSymbolAddress((void**)&pxh, g_xh);
    cudaGetSymbolAddress((void**)&pxl, g_xl);
    cudaGetSymbolAddress((void**)&phh, g_hh);
    cudaGetSymbolAddress((void**)&phl, g_hl);
    cudaGetSymbolAddress((void**)&pwh, g_wsh);
    cudaGetSymbolAddress((void**)&pwl, g_wsl);
    cudaGetSymbolAddress((void**)&pqh, g_qh);
    cudaGetSymbolAddress((void**)&pql, g_ql);
    cudaGetSymbolAddress((void**)&pkh, g_kh);
    cudaGetSymbolAddress((void**)&pkl, g_kl);
    cudaGetSymbolAddress((void**)&pvh, g_vh);
    cudaGetSymbolAddress((void**)&pvl, g_vl);

    weff_kernel<<<1, 256>>>(w_o, w_bd, b_o, b_bd);

    // splits
    split_kernel<<<BT*EE/4/256, 256>>>(x, pxh, pxl, BT*EE/4);
    split_kernel<<<EE*EE/4/256, 256>>>(w_in, pwh + 0*EE*EE, pwl + 0*EE*EE, EE*EE/4);
    split_kernel<<<EE*EE/4/256, 256>>>(w_q,  pwh + 1*EE*EE, pwl + 1*EE*EE, EE*EE/4);
    split_kernel<<<EE*EE/4/256, 256>>>(w_k,  pwh + 2*EE*EE, pwl + 2*EE*EE, EE*EE/4);
    split_kernel<<<EE*EE/4/256, 256>>>(w_v,  pwh + 3*EE*EE, pwl + 3*EE*EE, EE*EE/4);

    dim3 ggrid(BT / 64, EE / 64);
    // h = x @ w_in^T + b_in   (also emits hi/lo split of h)
    gemm_tc<<<ggrid, 128>>>(pxh, pxl, pwh + 0*EE*EE, pwl + 0*EE*EE, b_in, ph, phh, phl, 0);
    chs_kernel<<<dim3(BB, 32), 256>>>();
    // q, k, v
    gemm_tc<<<ggrid, 128>>>(phh, phl, pwh + 1*EE*EE, pwl + 1*EE*EE, b_q, nullptr, pqh, pql, 1);
    gemm_tc<<<ggrid, 128>>>(phh, phl, pwh + 2*EE*EE, pwl + 2*EE*EE, b_k, nullptr, pkh, pkl, 2);
    gemm_tc<<<ggrid, 128>>>(phh, phl, pwh + 3*EE*EE, pwl + 3*EE*EE, b_v, nullptr, pvh, pvl, 2);

    attn_mma<<<dim3(TT / 64, NBH), 128>>>();

    zsig_kernel<<<BT / 256, 256>>>();

    finalize_kernel<<<BB, 256>>>(w_pr, b_pr, out);
}